// round 14
// baseline (speedup 1.0000x reference)
#include <cuda_runtime.h>
#include <cuda_fp16.h>
#include <cstdint>
#include <cstddef>

#define NPAPER   100000
#define NSOFT    10000
#define EMB      256
#define HID      128
#define NEDGE    500000
#define NLBL     200000

// ---------------------------------------------------------------------------
// Scratch buffers (device globals — no runtime allocation allowed)
// ---------------------------------------------------------------------------
__device__ float  g_P0[(size_t)NPAPER * HID];
__device__ float  g_P1[(size_t)NPAPER * HID];
__device__ float  g_P2[(size_t)NPAPER * HID];
__device__ float  g_S0[(size_t)NSOFT * HID];
__device__ float  g_S1[(size_t)NSOFT * HID];
__device__ float  g_S2[(size_t)NSOFT * HID];
__device__ float  g_S3[(size_t)NSOFT * HID];
__device__ float  g_S4[(size_t)NSOFT * HID];
// fp16 gather tables (agg inputs)
__device__ __half g_P0h[(size_t)NPAPER * HID];
__device__ __half g_P1h[(size_t)NPAPER * HID];
__device__ __half g_S4h[(size_t)NSOFT * HID];
__device__ __half g_S5h[(size_t)NSOFT * HID];
// CSR machinery
__device__ int    g_cntP[NPAPER];
__device__ int    g_cntS[NSOFT];
__device__ int    g_offP[NPAPER];
__device__ int    g_offS[NSOFT];
__device__ int    g_bsum[1024];    // paper-scan block sums
__device__ int    g_bsum2[1024];   // software-scan block sums
__device__ int    g_csrP[NEDGE];
__device__ int    g_csrS[NEDGE];
// folded classifier weights / bias
__device__ float  g_W4[4 * HID * HID];
__device__ float  g_cvec[HID];

// ---------------------------------------------------------------------------
// Helpers
// ---------------------------------------------------------------------------
__device__ __forceinline__ uint32_t smem_u32(const void* p) {
    uint32_t a;
    asm("{ .reg .u64 t; cvta.to.shared.u64 t, %1; cvt.u32.u64 %0, t; }"
        : "=r"(a) : "l"(p));
    return a;
}

__device__ __forceinline__ uint32_t f32_to_tf32(float f) {
    uint32_t r;
    asm("cvt.rna.tf32.f32 %0, %1;" : "=r"(r) : "f"(f));
    return r;
}

__device__ __forceinline__ void cp16z(void* smem, const void* gmem, bool valid) {
    uint32_t s = smem_u32(smem);
    int sz = valid ? 16 : 0;
    asm volatile("cp.async.ca.shared.global [%0], [%1], 16, %2;"
                 :: "r"(s), "l"(gmem), "r"(sz));
}
__device__ __forceinline__ void cp16(void* smem, const void* gmem) {
    uint32_t s = smem_u32(smem);
    asm volatile("cp.async.ca.shared.global [%0], [%1], 16;"
                 :: "r"(s), "l"(gmem));
}
#define CP_COMMIT() asm volatile("cp.async.commit_group;" ::: "memory")
#define CP_WAIT(n)  asm volatile("cp.async.wait_group %0;" :: "n"(n) : "memory")

__device__ __forceinline__ void mma_tf32(float* d, const uint32_t* a, const uint32_t* b) {
    asm volatile(
        "mma.sync.aligned.m16n8k8.row.col.f32.tf32.tf32.f32 "
        "{%0,%1,%2,%3}, {%4,%5,%6,%7}, {%8,%9}, {%0,%1,%2,%3};"
        : "+f"(d[0]), "+f"(d[1]), "+f"(d[2]), "+f"(d[3])
        : "r"(a[0]), "r"(a[1]), "r"(a[2]), "r"(a[3]),
          "r"(b[0]), "r"(b[1]));
}

// ---------------------------------------------------------------------------
// Tensor-core GEMM via mma.sync tf32, 3xTF32 split for ~fp32 accuracy.
//   acc = A0@W0 (+ A1@W1 if DUAL) (+bias) (+C accum) (+gather add) (relu)
//   Stores: fp32 to C (if C != null), fp16 to Ch (if Ch != null).
// Tile 128x128 per CTA, 256 threads; BK=32 double-buffered cp.async.
// ---------------------------------------------------------------------------
#define A_STRIDE 36
#define B_STRIDE 136
#define A_BUF    (128 * A_STRIDE)
#define B_BUF    (32 * B_STRIDE)
#define MM_SMEM  ((2 * A_BUF + 2 * B_BUF) * 4)

template<bool DUAL, bool GATHER, bool ACCUM, bool RELU>
__global__ void __launch_bounds__(256) mma_gemm(
    const float* __restrict__ A0, int lda0,
    const float* __restrict__ A1, int lda1,
    const float* __restrict__ W0, const float* __restrict__ W1,
    const float* __restrict__ bias,
    const float* __restrict__ gtab, const int* __restrict__ gidx,
    float* __restrict__ C, __half* __restrict__ Ch, int M)
{
    extern __shared__ float sm[];
    float* aS_base = sm;
    float* bS_base = sm + 2 * A_BUF;

    const int tid  = threadIdx.x;
    const int wid  = tid >> 5;
    const int lane = tid & 31;
    const int wm   = wid & 3;
    const int wn   = wid >> 2;
    const int row0 = blockIdx.x * 128;
    const int KCH  = DUAL ? 8 : 4;

    float acc[2][8][4];
#pragma unroll
    for (int mt = 0; mt < 2; mt++)
#pragma unroll
        for (int nt = 0; nt < 8; nt++)
#pragma unroll
            for (int q = 0; q < 4; q++) acc[mt][nt][q] = 0.f;

    auto prefetch = [&](int c) {
        int buf = c & 1;
        const float* Asrc = (DUAL && c >= 4) ? A1 : A0;
        int lda          = (DUAL && c >= 4) ? lda1 : lda0;
        const float* Wsrc = (DUAL && c >= 4) ? W1 : W0;
        int ko = (DUAL ? (c & 3) : c) * 32;
        float* aS = aS_base + buf * A_BUF;
        float* bS = bS_base + buf * B_BUF;
#pragma unroll
        for (int i = 0; i < 4; i++) {
            int j   = tid + i * 256;
            int r   = j >> 3;
            int kq  = j & 7;
            int grow = row0 + r;
            cp16z(aS + r * A_STRIDE + kq * 4,
                  Asrc + (size_t)grow * lda + ko + kq * 4, grow < M);
        }
#pragma unroll
        for (int i = 0; i < 4; i++) {
            int j  = tid + i * 256;
            int k  = j >> 5;
            int nq = j & 31;
            cp16(bS + k * B_STRIDE + nq * 4,
                 Wsrc + (size_t)(ko + k) * 128 + nq * 4);
        }
        CP_COMMIT();
    };

    prefetch(0);
    for (int c = 0; c < KCH; c++) {
        if (c + 1 < KCH) { prefetch(c + 1); CP_WAIT(1); }
        else             { CP_WAIT(0); }
        __syncthreads();

        const float* aS = aS_base + (c & 1) * A_BUF;
        const float* bS = bS_base + (c & 1) * B_BUF;
#pragma unroll
        for (int k8 = 0; k8 < 4; k8++) {
            const int kb = k8 * 8;
            uint32_t ahi[2][4], alo[2][4];
#pragma unroll
            for (int mt = 0; mt < 2; mt++) {
                int rbase = wm * 32 + mt * 16 + (lane >> 2);
#pragma unroll
                for (int q = 0; q < 4; q++) {
                    int r = rbase + ((q & 1) ? 8 : 0);
                    int cc = kb + (lane & 3) + ((q & 2) ? 4 : 0);
                    float f = aS[r * A_STRIDE + cc];
                    uint32_t h = f32_to_tf32(f);
                    ahi[mt][q] = h;
                    alo[mt][q] = f32_to_tf32(f - __uint_as_float(h));
                }
            }
            uint32_t bhi[8][2], blo[8][2];
#pragma unroll
            for (int nt = 0; nt < 8; nt++) {
                int nn = wn * 64 + nt * 8 + (lane >> 2);
#pragma unroll
                for (int q = 0; q < 2; q++) {
                    int kk = kb + (lane & 3) + q * 4;
                    float f = bS[kk * B_STRIDE + nn];
                    uint32_t h = f32_to_tf32(f);
                    bhi[nt][q] = h;
                    blo[nt][q] = f32_to_tf32(f - __uint_as_float(h));
                }
            }
#pragma unroll
            for (int mt = 0; mt < 2; mt++)
#pragma unroll
                for (int nt = 0; nt < 8; nt++) {
                    mma_tf32(acc[mt][nt], ahi[mt], bhi[nt]);
                    mma_tf32(acc[mt][nt], ahi[mt], blo[nt]);
                    mma_tf32(acc[mt][nt], alo[mt], bhi[nt]);
                }
        }
        __syncthreads();
    }

    // ---- epilogue ----
#pragma unroll
    for (int mt = 0; mt < 2; mt++)
#pragma unroll
        for (int half = 0; half < 2; half++) {
            int row = row0 + wm * 32 + mt * 16 + (lane >> 2) + half * 8;
            if (row >= M) continue;
            int gi = 0;
            if (GATHER) gi = gidx[row];
#pragma unroll
            for (int nt = 0; nt < 8; nt++) {
                int col = wn * 64 + nt * 8 + 2 * (lane & 3);
                float2 v = make_float2(acc[mt][nt][half * 2],
                                       acc[mt][nt][half * 2 + 1]);
                if (bias) {
                    float2 b2 = *(const float2*)(bias + col);
                    v.x += b2.x; v.y += b2.y;
                }
                if (ACCUM) {
                    float2 c2 = *(const float2*)(C + (size_t)row * 128 + col);
                    v.x += c2.x; v.y += c2.y;
                }
                if (GATHER) {
                    float2 g2 = *(const float2*)(gtab + (size_t)gi * 128 + col);
                    v.x += g2.x; v.y += g2.y;
                }
                if (RELU) { v.x = fmaxf(v.x, 0.f); v.y = fmaxf(v.y, 0.f); }
                if (!ACCUM) {   // when ACCUM, C is always the fp32 dst (non-null)
                    if (C) *(float2*)(C + (size_t)row * 128 + col) = v;
                } else {
                    *(float2*)(C + (size_t)row * 128 + col) = v;
                }
                if (Ch) *(__half2*)(Ch + (size_t)row * 128 + col) =
                            __floats2half2_rn(v.x, v.y);
            }
        }
}

// ---------------------------------------------------------------------------
// 4x fused 128x128x128 fp32 weight-product GEMM (exact; tiny)
// ---------------------------------------------------------------------------
struct WProd { const float* A[4]; const float* B[4]; float* C[4]; };

__global__ void __launch_bounds__(256) wprod_kernel(WProd wp)
{
    __shared__ float As[16][132];
    __shared__ float Wsm[16][132];
    const float* A = wp.A[blockIdx.x];
    const float* W = wp.B[blockIdx.x];
    float*       C = wp.C[blockIdx.x];

    const int tid = threadIdx.x;
    const int tx  = tid & 15;
    const int ty  = tid >> 4;
    const int ar  = tid >> 2;
    const int ac  = (tid & 3) << 2;
    const int wr  = tid >> 5;
    const int wc  = (tid & 31) << 2;

    float acc[8][8];
#pragma unroll
    for (int i = 0; i < 8; i++)
#pragma unroll
        for (int j = 0; j < 8; j++) acc[i][j] = 0.f;

    for (int k0 = 0; k0 < 128; k0 += 16) {
#pragma unroll
        for (int p = 0; p < 2; p++) {
            int r = ar + p * 64;
            float4 v = *(const float4*)(A + (size_t)r * 128 + k0 + ac);
            As[ac + 0][r] = v.x; As[ac + 1][r] = v.y;
            As[ac + 2][r] = v.z; As[ac + 3][r] = v.w;
        }
#pragma unroll
        for (int p = 0; p < 2; p++) {
            int r = wr + p * 8;
            *(float4*)&Wsm[r][wc] = *(const float4*)(W + (size_t)(k0 + r) * 128 + wc);
        }
        __syncthreads();
#pragma unroll
        for (int kk = 0; kk < 16; kk++) {
            float a[8], b[8];
            *(float4*)(a)     = *(const float4*)&As[kk][ty * 8];
            *(float4*)(a + 4) = *(const float4*)&As[kk][ty * 8 + 4];
            *(float4*)(b)     = *(const float4*)&Wsm[kk][tx * 8];
            *(float4*)(b + 4) = *(const float4*)&Wsm[kk][tx * 8 + 4];
#pragma unroll
            for (int i = 0; i < 8; i++)
#pragma unroll
                for (int j = 0; j < 8; j++)
                    acc[i][j] = fmaf(a[i], b[j], acc[i][j]);
        }
        __syncthreads();
    }
#pragma unroll
    for (int i = 0; i < 8; i++) {
        int r = ty * 8 + i;
#pragma unroll
        for (int j = 0; j < 8; j += 4)
            *(float4*)(C + (size_t)r * 128 + tx * 8 + j) =
                make_float4(acc[i][j], acc[i][j+1], acc[i][j+2], acc[i][j+3]);
    }
}

__global__ void cvec_kernel(const float* __restrict__ bc1,
                            const float* __restrict__ bl2_sp,
                            const float* __restrict__ bl2_ps,
                            const float* __restrict__ Wc1,
                            float* __restrict__ cvec)
{
    int j = threadIdx.x;
    float c = bc1[j];
    for (int k = 0; k < 128; k++) {
        c += bl2_sp[k] * Wc1[(size_t)k * 128 + j];
        c += bl2_ps[k] * Wc1[(size_t)(128 + k) * 128 + j];
    }
    cvec[j] = c;
}

// ---------------------------------------------------------------------------
// CSR build
// ---------------------------------------------------------------------------
__global__ void hist_kernel(const int* __restrict__ src, const int* __restrict__ dst,
                            int* cntP, int* cntS, int E)
{
    int i = blockIdx.x * blockDim.x + threadIdx.x;
    if (i < E) {
        atomicAdd(&cntP[src[i]], 1);
        atomicAdd(&cntS[dst[i]], 1);
    }
}

__global__ void scan1_kernel(const int* __restrict__ in, int* __restrict__ out_excl,
                             int* __restrict__ bsums, int N)
{
    __shared__ int sh[2][1024];
    int t = threadIdx.x;
    int i = blockIdx.x * 1024 + t;
    int x = (i < N) ? in[i] : 0;
    sh[0][t] = x;
    __syncthreads();
    int cur = 0;
#pragma unroll
    for (int off = 1; off < 1024; off <<= 1) {
        int v = sh[cur][t];
        if (t >= off) v += sh[cur][t - off];
        sh[cur ^ 1][t] = v;
        __syncthreads();
        cur ^= 1;
    }
    int incl = sh[cur][t];
    if (i < N) out_excl[i] = incl - x;
    if (t == 1023) bsums[blockIdx.x] = incl;
}

__global__ void scan2_kernel(int* __restrict__ b, int nb)
{
    __shared__ int sh[2][1024];
    int t = threadIdx.x;
    int x = (t < nb) ? b[t] : 0;
    sh[0][t] = x;
    __syncthreads();
    int cur = 0;
#pragma unroll
    for (int off = 1; off < 1024; off <<= 1) {
        int v = sh[cur][t];
        if (t >= off) v += sh[cur][t - off];
        sh[cur ^ 1][t] = v;
        __syncthreads();
        cur ^= 1;
    }
    if (t < nb) b[t] = sh[cur][t] - x;
}

__global__ void scan3_kernel(int* __restrict__ out, const int* __restrict__ bsums, int N)
{
    int i = blockIdx.x * blockDim.x + threadIdx.x;
    if (i < N) out[i] += bsums[i >> 10];
}

__global__ void fill_kernel(const int* __restrict__ src, const int* __restrict__ dst,
                            const int* __restrict__ offP, const int* __restrict__ offS,
                            int* curP, int* curS,
                            int* __restrict__ csrP, int* __restrict__ csrS, int E)
{
    int e = blockIdx.x * blockDim.x + threadIdx.x;
    if (e >= E) return;
    int s = src[e];
    int d = dst[e];
    int pS = offS[d] + atomicAdd(&curS[d], 1);
    csrS[pS] = s;
    int pP = offP[s] + atomicAdd(&curP[s], 1);
    csrP[pP] = d;
}

// ---------------------------------------------------------------------------
// Gather-mean aggregation, fp16 input tables (half the gather traffic)
// ---------------------------------------------------------------------------
__global__ void agg_kernel_h(const __half* __restrict__ feat,
                             const int* __restrict__ off, const int* __restrict__ cnt,
                             const int* __restrict__ idx,
                             float* __restrict__ out, int M)
{
    int gtid = blockIdx.x * blockDim.x + threadIdx.x;
    int n    = gtid >> 5;
    int lane = gtid & 31;
    if (n >= M) return;
    int start = off[n];
    int deg   = cnt[n];
    float4 acc = make_float4(0.f, 0.f, 0.f, 0.f);
    int j = 0;
    for (; j + 1 < deg; j += 2) {
        int i0 = __ldg(&idx[start + j]);
        int i1 = __ldg(&idx[start + j + 1]);
        uint2 r0 = *(const uint2*)(feat + (size_t)i0 * 128 + lane * 4);
        uint2 r1 = *(const uint2*)(feat + (size_t)i1 * 128 + lane * 4);
        float2 a0 = __half22float2(*(__half2*)&r0.x);
        float2 a1 = __half22float2(*(__half2*)&r0.y);
        float2 b0 = __half22float2(*(__half2*)&r1.x);
        float2 b1 = __half22float2(*(__half2*)&r1.y);
        acc.x += a0.x + b0.x; acc.y += a0.y + b0.y;
        acc.z += a1.x + b1.x; acc.w += a1.y + b1.y;
    }
    if (j < deg) {
        int i0 = __ldg(&idx[start + j]);
        uint2 r0 = *(const uint2*)(feat + (size_t)i0 * 128 + lane * 4);
        float2 a0 = __half22float2(*(__half2*)&r0.x);
        float2 a1 = __half22float2(*(__half2*)&r0.y);
        acc.x += a0.x; acc.y += a0.y; acc.z += a1.x; acc.w += a1.y;
    }
    float s = 1.f / fmaxf((float)deg, 1.f);
    acc.x *= s; acc.y *= s; acc.z *= s; acc.w *= s;
    *(float4*)(out + (size_t)n * 128 + lane * 4) = acc;
}

// ---------------------------------------------------------------------------
// Edge classifier: 2 labels per warp (16 lanes each).
// ---------------------------------------------------------------------------
__global__ void classify_kernel(const float* __restrict__ up, const float* __restrict__ us,
                                const int* __restrict__ lp, const int* __restrict__ ls,
                                const float* __restrict__ cvec, const float* __restrict__ wc2,
                                const float* __restrict__ bc2,
                                float* __restrict__ out, int L)
{
    int gtid = blockIdx.x * blockDim.x + threadIdx.x;
    int l    = gtid >> 4;
    int sub  = gtid & 15;
    if (l >= L) return;
    int ip = lp[l];
    int is = ls[l];
    const float4* pa = (const float4*)(up   + (size_t)ip * 128 + sub * 8);
    const float4* pb = (const float4*)(us   + (size_t)is * 128 + sub * 8);
    const float4* pc = (const float4*)(cvec + sub * 8);
    const float4* pw = (const float4*)(wc2  + sub * 8);
    float4 a0 = pa[0], a1 = pa[1];
    float4 b0 = pb[0], b1 = pb[1];
    float4 c0 = pc[0], c1 = pc[1];
    float4 w0 = pw[0], w1 = pw[1];
    float s = fmaxf(a0.x + b0.x + c0.x, 0.f) * w0.x
            + fmaxf(a0.y + b0.y + c0.y, 0.f) * w0.y
            + fmaxf(a0.z + b0.z + c0.z, 0.f) * w0.z
            + fmaxf(a0.w + b0.w + c0.w, 0.f) * w0.w
            + fmaxf(a1.x + b1.x + c1.x, 0.f) * w1.x
            + fmaxf(a1.y + b1.y + c1.y, 0.f) * w1.y
            + fmaxf(a1.z + b1.z + c1.z, 0.f) * w1.z
            + fmaxf(a1.w + b1.w + c1.w, 0.f) * w1.w;
#pragma unroll
    for (int o = 8; o > 0; o >>= 1) s += __shfl_xor_sync(0xffffffffu, s, o);
    if (sub == 0) out[l] = s + bc2[0];
}

// ---------------------------------------------------------------------------
// Stream/event context (host-side objects only; created once)
// ---------------------------------------------------------------------------
static cudaStream_t sA, sB, sC;
static cudaEvent_t  evRoot, evHist, evScanS, evCSR, evFusS, evFusP, evW, evB,
                    evHs, evHp, evA, evC;
static int          g_streams_ok = -1;

static bool init_streams()
{
    bool ok = true;
    ok &= cudaStreamCreateWithFlags(&sA, cudaStreamNonBlocking) == cudaSuccess;
    ok &= cudaStreamCreateWithFlags(&sB, cudaStreamNonBlocking) == cudaSuccess;
    ok &= cudaStreamCreateWithFlags(&sC, cudaStreamNonBlocking) == cudaSuccess;
    cudaEvent_t* evs[12] = {&evRoot, &evHist, &evScanS, &evCSR, &evFusS, &evFusP,
                            &evW, &evB, &evHs, &evHp, &evA, &evC};
    for (int i = 0; i < 12; i++)
        ok &= cudaEventCreateWithFlags(evs[i], cudaEventDisableTiming) == cudaSuccess;
    return ok;
}

// ---------------------------------------------------------------------------
// Launch
// ---------------------------------------------------------------------------
extern "C" void kernel_launch(void* const* d_in, const int* in_sizes, int n_in,
                              void* d_out, int out_size)
{
    (void)in_sizes; (void)n_in; (void)out_size;

    const float* x_paper    = (const float*)d_in[0];
    const float* x_software = (const float*)d_in[1];
    const int*   paper_id   = (const int*)d_in[2];
    const int*   software_id= (const int*)d_in[3];
    const int*   edge_src   = (const int*)d_in[4];
    const int*   edge_dst   = (const int*)d_in[5];
    const int*   lbl_paper  = (const int*)d_in[6];
    const int*   lbl_soft   = (const int*)d_in[7];
    const float* paper_emb  = (const float*)d_in[8];
    const float* soft_emb   = (const float*)d_in[9];
    const float* Wp   = (const float*)d_in[10]; const float* bp    = (const float*)d_in[11];
    const float* Wso  = (const float*)d_in[12]; const float* bso   = (const float*)d_in[13];
    const float* Wl1_ps=(const float*)d_in[14]; const float* bl1_ps=(const float*)d_in[15];
    const float* Wr1_ps=(const float*)d_in[16];
    const float* Wl1_sp=(const float*)d_in[17]; const float* bl1_sp=(const float*)d_in[18];
    const float* Wr1_sp=(const float*)d_in[19];
    const float* Wl2_ps=(const float*)d_in[20]; const float* bl2_ps=(const float*)d_in[21];
    const float* Wr2_ps=(const float*)d_in[22];
    const float* Wl2_sp=(const float*)d_in[23]; const float* bl2_sp=(const float*)d_in[24];
    const float* Wr2_sp=(const float*)d_in[25];
    const float* Wc1  = (const float*)d_in[26]; const float* bc1   = (const float*)d_in[27];
    const float* Wc2  = (const float*)d_in[28]; const float* bc2   = (const float*)d_in[29];
    float* out = (float*)d_out;

    float *pP0, *pP1, *pP2, *pS0, *pS1, *pS2, *pS3, *pS4, *pW4, *pCvec;
    __half *pP0h, *pP1h, *pS4h, *pS5h;
    int *pCntP, *pCntS, *pOffP, *pOffS, *pBsum, *pBsum2, *pCsrP, *pCsrS;
    cudaGetSymbolAddress((void**)&pP0, g_P0);
    cudaGetSymbolAddress((void**)&pP1, g_P1);
    cudaGetSymbolAddress((void**)&pP2, g_P2);
    cudaGetSymbolAddress((void**)&pS0, g_S0);
    cudaGetSymbolAddress((void**)&pS1, g_S1);
    cudaGetSymbolAddress((void**)&pS2, g_S2);
    cudaGetSymbolAddress((void**)&pS3, g_S3);
    cudaGetSymbolAddress((void**)&pS4, g_S4);
    cudaGetSymbolAddress((void**)&pP0h, g_P0h);
    cudaGetSymbolAddress((void**)&pP1h, g_P1h);
    cudaGetSymbolAddress((void**)&pS4h, g_S4h);
    cudaGetSymbolAddress((void**)&pS5h, g_S5h);
    cudaGetSymbolAddress((void**)&pW4, g_W4);
    cudaGetSymbolAddress((void**)&pCvec, g_cvec);
    cudaGetSymbolAddress((void**)&pCntP, g_cntP);
    cudaGetSymbolAddress((void**)&pCntS, g_cntS);
    cudaGetSymbolAddress((void**)&pOffP, g_offP);
    cudaGetSymbolAddress((void**)&pOffS, g_offS);
    cudaGetSymbolAddress((void**)&pBsum, g_bsum);
    cudaGetSymbolAddress((void**)&pBsum2, g_bsum2);
    cudaGetSymbolAddress((void**)&pCsrP, g_csrP);
    cudaGetSymbolAddress((void**)&pCsrS, g_csrS);

    cudaFuncSetAttribute(mma_gemm<true,  true,  false, false>, cudaFuncAttributeMaxDynamicSharedMemorySize, MM_SMEM);
    cudaFuncSetAttribute(mma_gemm<true,  false, false, true >, cudaFuncAttributeMaxDynamicSharedMemorySize, MM_SMEM);
    cudaFuncSetAttribute(mma_gemm<true,  false, false, false>, cudaFuncAttributeMaxDynamicSharedMemorySize, MM_SMEM);
    cudaFuncSetAttribute(mma_gemm<false, false, false, false>, cudaFuncAttributeMaxDynamicSharedMemorySize, MM_SMEM);
    cudaFuncSetAttribute(mma_gemm<false, false, true,  true >, cudaFuncAttributeMaxDynamicSharedMemorySize, MM_SMEM);
    cudaFuncSetAttribute(mma_gemm<false, false, true,  false>, cudaFuncAttributeMaxDynamicSharedMemorySize, MM_SMEM);

    if (g_streams_ok < 0) g_streams_ok = init_streams() ? 1 : 0;

    const int E = NEDGE, L = NLBL;
    const int gP = (NPAPER + 127) / 128;
    const int gS = (NSOFT  + 127) / 128;
    const int aggPBlocks = (int)(((long long)NPAPER * 32 + 255) / 256);
    const int aggSBlocks = (int)(((long long)NSOFT  * 32 + 255) / 256);
    const int nbP = (NPAPER + 1023) / 1024;
    const int nbS = (NSOFT  + 1023) / 1024;
    const int clsBlocks = (int)(((long long)L * 16 + 255) / 256);

    const float* Wc1_top = Wc1;
    const float* Wc1_bot = Wc1 + 128 * 128;
    WProd wp;
    wp.A[0] = Wl2_sp; wp.B[0] = Wc1_top; wp.C[0] = pW4 + 0 * 16384;  // WA
    wp.A[1] = Wr2_sp; wp.B[1] = Wc1_top; wp.C[1] = pW4 + 1 * 16384;  // WB
    wp.A[2] = Wl2_ps; wp.B[2] = Wc1_bot; wp.C[2] = pW4 + 2 * 16384;  // WC
    wp.A[3] = Wr2_ps; wp.B[3] = Wc1_bot; wp.C[3] = pW4 + 3 * 16384;  // WD

    if (g_streams_ok == 1) {
        // ========== forked-capture parallel schedule (R13 + fp16 gather) ====
        cudaEventRecord(evRoot, 0);
        cudaStreamWaitEvent(sA, evRoot, 0);
        cudaStreamWaitEvent(sB, evRoot, 0);
        cudaStreamWaitEvent(sC, evRoot, 0);

        // sA: CSR build (paper scan local; software scan forked to sB)
        cudaMemsetAsync(pCntP, 0, NPAPER * sizeof(int), sA);
        cudaMemsetAsync(pCntS, 0, NSOFT  * sizeof(int), sA);
        hist_kernel<<<(E + 255) / 256, 256, 0, sA>>>(edge_src, edge_dst, pCntP, pCntS, E);
        cudaEventRecord(evHist, sA);
        scan1_kernel<<<nbP, 1024, 0, sA>>>(pCntP, pOffP, pBsum, NPAPER);
        scan2_kernel<<<1, 1024, 0, sA>>>(pBsum, nbP);
        scan3_kernel<<<(NPAPER + 255) / 256, 256, 0, sA>>>(pOffP, pBsum, NPAPER);
        cudaMemsetAsync(pCntP, 0, NPAPER * sizeof(int), sA);
        cudaStreamWaitEvent(sB, evHist, 0);
        scan1_kernel<<<nbS, 1024, 0, sB>>>(pCntS, pOffS, pBsum2, NSOFT);
        scan2_kernel<<<1, 1024, 0, sB>>>(pBsum2, nbS);
        scan3_kernel<<<(NSOFT + 255) / 256, 256, 0, sB>>>(pOffS, pBsum2, NSOFT);
        cudaMemsetAsync(pCntS, 0, NSOFT * sizeof(int), sB);
        cudaEventRecord(evScanS, sB);
        cudaStreamWaitEvent(sA, evScanS, 0);
        fill_kernel<<<(E + 255) / 256, 256, 0, sA>>>(edge_src, edge_dst, pOffP, pOffS,
                                                     pCntP, pCntS, pCsrP, pCsrS, E);
        cudaEventRecord(evCSR, sA);

        // sB: weight products + cvec
        wprod_kernel<<<4, 256, 0, sB>>>(wp);
        cudaEventRecord(evW, sB);
        cvec_kernel<<<1, 128, 0, sB>>>(bc1, bl2_sp, bl2_ps, Wc1, pCvec);
        cudaEventRecord(evB, sB);

        // s0: paper input fusion (fp32 P0 + fp16 P0h)
        mma_gemm<true, true, false, false><<<gP, 256, MM_SMEM>>>(
            x_paper, 256, x_paper + 128, 256, Wp, Wp + 128 * 128,
            bp, paper_emb, paper_id, pP0, pP0h, NPAPER);
        cudaEventRecord(evFusP, 0);

        // sC: software fusion -> sp-direction chain -> h_p
        mma_gemm<true, true, false, false><<<gS, 256, MM_SMEM, sC>>>(
            x_software, 256, x_software + 128, 256, Wso, Wso + 128 * 128,
            bso, soft_emb, software_id, pS0, nullptr, NSOFT);
        cudaEventRecord(evFusS, sC);
        mma_gemm<false, false, false, false><<<gS, 256, MM_SMEM, sC>>>(
            pS0, 128, nullptr, 0, Wl1_sp, nullptr,
            nullptr, nullptr, nullptr, nullptr, pS4h, NSOFT);        // S4h (fp16 only)
        cudaStreamWaitEvent(sC, evCSR, 0);
        agg_kernel_h<<<aggPBlocks, 256, 0, sC>>>(pS4h, pOffP, pCntP, pCsrP, pP1, NPAPER);
        cudaStreamWaitEvent(sC, evFusP, 0);
        mma_gemm<false, false, true, true><<<gP, 256, MM_SMEM, sC>>>(
            pP0, 128, nullptr, 0, Wr1_sp, nullptr,
            bl1_sp, nullptr, nullptr, pP1, pP1h, NPAPER);            // h_p (fp32+fp16)
        cudaEventRecord(evHp, sC);

        // sA: ps-direction chain + u_p chain
        cudaStreamWaitEvent(sA, evFusP, 0);
        agg_kernel_h<<<aggSBlocks, 256, 0, sA>>>(pP0h, pOffS, pCntS, pCsrS, pS3, NSOFT);
        cudaStreamWaitEvent(sA, evFusS, 0);
        mma_gemm<true, false, false, true><<<gS, 256, MM_SMEM, sA>>>(
            pS3, 128, pS0, 128, Wl1_ps, Wr1_ps,
            bl1_ps, nullptr, nullptr, pS1, nullptr, NSOFT);          // h_s
        cudaEventRecord(evHs, sA);
        cudaStreamWaitEvent(sA, evW, 0);
        mma_gemm<false, false, false, false><<<gS, 256, MM_SMEM, sA>>>(
            pS1, 128, nullptr, 0, pW4 + 0 * 16384, nullptr,
            nullptr, nullptr, nullptr, nullptr, pS5h, NSOFT);        // h_s @ WA -> S5h
        agg_kernel_h<<<aggPBlocks, 256, 0, sA>>>(pS5h, pOffP, pCntP, pCsrP, pP2, NPAPER);
        cudaStreamWaitEvent(sA, evHp, 0);
        mma_gemm<false, false, true, false><<<gP, 256, MM_SMEM, sA>>>(
            pP1, 128, nullptr, 0, pW4 + 1 * 16384, nullptr,
            nullptr, nullptr, nullptr, pP2, nullptr, NPAPER);        // u_p (accum P2)
        cudaEventRecord(evA, sA);

        // sC: u_s chain (after h_p on same stream)
        agg_kernel_h<<<aggSBlocks, 256, 0, sC>>>(pP1h, pOffS, pCntS, pCsrS, pS4, NSOFT);
        cudaStreamWaitEvent(sC, evHs, 0);
        cudaStreamWaitEvent(sC, evW, 0);
        mma_gemm<true, false, false, false><<<gS, 256, MM_SMEM, sC>>>(
            pS4, 128, pS1, 128, pW4 + 2 * 16384, pW4 + 3 * 16384,
            nullptr, nullptr, nullptr, pS2, nullptr, NSOFT);         // u_s
        cudaEventRecord(evC, sC);

        // s0: join + classify
        cudaStreamWaitEvent(0, evA, 0);
        cudaStreamWaitEvent(0, evC, 0);
        cudaStreamWaitEvent(0, evB, 0);
        classify_kernel<<<clsBlocks, 256>>>(
            pP2, pS2, lbl_paper, lbl_soft, pCvec, Wc2, bc2, out, L);
    } else {
        // ================= serial fallback =================
        cudaMemsetAsync(pCntP, 0, NPAPER * sizeof(int));
        cudaMemsetAsync(pCntS, 0, NSOFT  * sizeof(int));
        hist_kernel<<<(E + 255) / 256, 256>>>(edge_src, edge_dst, pCntP, pCntS, E);
        scan1_kernel<<<nbS, 1024>>>(pCntS, pOffS, pBsum2, NSOFT);
        scan2_kernel<<<1, 1024>>>(pBsum2, nbS);
        scan3_kernel<<<(NSOFT + 255) / 256, 256>>>(pOffS, pBsum2, NSOFT);
        scan1_kernel<<<nbP, 1024>>>(pCntP, pOffP, pBsum, NPAPER);
        scan2_kernel<<<1, 1024>>>(pBsum, nbP);
        scan3_kernel<<<(NPAPER + 255) / 256, 256>>>(pOffP, pBsum, NPAPER);
        cudaMemsetAsync(pCntP, 0, NPAPER * sizeof(int));
        cudaMemsetAsync(pCntS, 0, NSOFT  * sizeof(int));
        fill_kernel<<<(E + 255) / 256, 256>>>(edge_src, edge_dst, pOffP, pOffS,
                                              pCntP, pCntS, pCsrP, pCsrS, E);
        wprod_kernel<<<4, 256>>>(wp);
        cvec_kernel<<<1, 128>>>(bc1, bl2_sp, bl2_ps, Wc1, pCvec);
        mma_gemm<true, true, false, false><<<gP, 256, MM_SMEM>>>(
            x_paper, 256, x_paper + 128, 256, Wp, Wp + 128 * 128,
            bp, paper_emb, paper_id, pP0, pP0h, NPAPER);
        mma_gemm<true, true, false, false><<<gS, 256, MM_SMEM>>>(
            x_software, 256, x_software + 128, 256, Wso, Wso + 128 * 128,
            bso, soft_emb, software_id, pS0, nullptr, NSOFT);
        agg_kernel_h<<<aggSBlocks, 256>>>(pP0h, pOffS, pCntS, pCsrS, pS3, NSOFT);
        mma_gemm<true, false, false, true><<<gS, 256, MM_SMEM>>>(
            pS3, 128, pS0, 128, Wl1_ps, Wr1_ps,
            bl1_ps, nullptr, nullptr, pS1, nullptr, NSOFT);
        mma_gemm<false, false, false, false><<<gS, 256, MM_SMEM>>>(
            pS0, 128, nullptr, 0, Wl1_sp, nullptr,
            nullptr, nullptr, nullptr, nullptr, pS4h, NSOFT);
        agg_kernel_h<<<aggPBlocks, 256>>>(pS4h, pOffP, pCntP, pCsrP, pP1, NPAPER);
        mma_gemm<false, false, true, true><<<gP, 256, MM_SMEM>>>(
            pP0, 128, nullptr, 0, Wr1_sp, nullptr,
            bl1_sp, nullptr, nullptr, pP1, pP1h, NPAPER);
        mma_gemm<false, false, false, false><<<gS, 256, MM_SMEM>>>(
            pS1, 128, nullptr, 0, pW4 + 0 * 16384, nullptr,
            nullptr, nullptr, nullptr, nullptr, pS5h, NSOFT);
        agg_kernel_h<<<aggPBlocks, 256>>>(pS5h, pOffP, pCntP, pCsrP, pP2, NPAPER);
        mma_gemm<false, false, true, false><<<gP, 256, MM_SMEM>>>(
            pP1, 128, nullptr, 0, pW4 + 1 * 16384, nullptr,
            nullptr, nullptr, nullptr, pP2, nullptr, NPAPER);
        agg_kernel_h<<<aggSBlocks, 256>>>(pP1h, pOffS, pCntS, pCsrS, pS4, NSOFT);
        mma_gemm<true, false, false, false><<<gS, 256, MM_SMEM>>>(
            pS4, 128, pS1, 128, pW4 + 2 * 16384, pW4 + 3 * 16384,
            nullptr, nullptr, nullptr, pS2, nullptr, NSOFT);
        classify_kernel<<<clsBlocks, 256>>>(
            pP2, pS2, lbl_paper, lbl_soft, pCvec, Wc2, bc2, out, L);
    }
}

// round 16
// speedup vs baseline: 1.1976x; 1.1976x over previous
#include <cuda_runtime.h>
#include <cuda_fp16.h>
#include <cstdint>
#include <cstddef>

#define NPAPER   100000
#define NSOFT    10000
#define EMB      256
#define HID      128
#define NEDGE    500000
#define NLBL     200000

// ---------------------------------------------------------------------------
// Scratch buffers (device globals — no runtime allocation allowed)
// ---------------------------------------------------------------------------
__device__ float g_P0[(size_t)NPAPER * HID];
__device__ float g_P1[(size_t)NPAPER * HID];
__device__ float g_P2[(size_t)NPAPER * HID];
__device__ float g_S0[(size_t)NSOFT * HID];
__device__ float g_S1[(size_t)NSOFT * HID];
__device__ float g_S2[(size_t)NSOFT * HID];
__device__ float g_S3[(size_t)NSOFT * HID];
__device__ float g_S4[(size_t)NSOFT * HID];
__device__ float g_S5[(size_t)NSOFT * HID];
// CSR machinery
__device__ int   g_cntP[NPAPER];
__device__ int   g_cntS[NSOFT];
__device__ int   g_offP[NPAPER];
__device__ int   g_offS[NSOFT];
__device__ int   g_bsum[1024];    // paper-scan block sums
__device__ int   g_bsum2[1024];   // software-scan block sums
__device__ int   g_csrP[NEDGE];
__device__ int   g_csrS[NEDGE];
// folded classifier weights / bias
__device__ float g_W4[4 * HID * HID];
__device__ float g_cvec[HID];

// ---------------------------------------------------------------------------
// Helpers
// ---------------------------------------------------------------------------
__device__ __forceinline__ uint32_t smem_u32(const void* p) {
    uint32_t a;
    asm("{ .reg .u64 t; cvta.to.shared.u64 t, %1; cvt.u32.u64 %0, t; }"
        : "=r"(a) : "l"(p));
    return a;
}

__device__ __forceinline__ void cp16z(void* smem, const void* gmem, bool valid) {
    uint32_t s = smem_u32(smem);
    int sz = valid ? 16 : 0;
    asm volatile("cp.async.ca.shared.global [%0], [%1], 16, %2;"
                 :: "r"(s), "l"(gmem), "r"(sz));
}
__device__ __forceinline__ void cp16(void* smem, const void* gmem) {
    uint32_t s = smem_u32(smem);
    asm volatile("cp.async.ca.shared.global [%0], [%1], 16;"
                 :: "r"(s), "l"(gmem));
}
#define CP_COMMIT() asm volatile("cp.async.commit_group;" ::: "memory")
#define CP_WAIT(n)  asm volatile("cp.async.wait_group %0;" :: "n"(n) : "memory")

// fp16 m16n8k16 MMA, f32 accumulate
__device__ __forceinline__ void mma_f16(float* d, const uint32_t* a, const uint32_t* b) {
    asm volatile(
        "mma.sync.aligned.m16n8k16.row.col.f32.f16.f16.f32 "
        "{%0,%1,%2,%3}, {%4,%5,%6,%7}, {%8,%9}, {%0,%1,%2,%3};"
        : "+f"(d[0]), "+f"(d[1]), "+f"(d[2]), "+f"(d[3])
        : "r"(a[0]), "r"(a[1]), "r"(a[2]), "r"(a[3]),
          "r"(b[0]), "r"(b[1]));
}

// split fp32 pair -> fp16 hi pair + fp16 residual pair (packed half2 as u32)
__device__ __forceinline__ void split_h2(float f0, float f1,
                                         uint32_t& hi, uint32_t& lo) {
    __half2 h = __floats2half2_rn(f0, f1);
    float2 hf = __half22float2(h);
    __half2 l = __floats2half2_rn(f0 - hf.x, f1 - hf.y);
    hi = *(uint32_t*)&h;
    lo = *(uint32_t*)&l;
}

// ---------------------------------------------------------------------------
// Tensor-core GEMM via mma.sync m16n8k16 fp16, 3-term split (~fp32 accuracy).
//   C[M,128] = A0[M,128](lda0) @ W0[128,128]
//            (+ A1[M,128](lda1) @ W1[128,128] if DUAL)
//            (+ bias) (+ C accum) (+ gather add) (relu)
// Tile 128x128 per CTA, 256 threads (8 warps: 4 along M x 2 along N).
// BK=32, cp.async double-buffered.  Warp tile 32x64.
// ---------------------------------------------------------------------------
#define A_STRIDE 36
#define B_STRIDE 136
#define A_BUF    (128 * A_STRIDE)
#define B_BUF    (32 * B_STRIDE)
#define MM_SMEM  ((2 * A_BUF + 2 * B_BUF) * 4)

template<bool DUAL, bool GATHER, bool ACCUM, bool RELU>
__global__ void __launch_bounds__(256) mma_gemm(
    const float* __restrict__ A0, int lda0,
    const float* __restrict__ A1, int lda1,
    const float* __restrict__ W0, const float* __restrict__ W1,
    const float* __restrict__ bias,
    const float* __restrict__ gtab, const int* __restrict__ gidx,
    float* __restrict__ C, int M)
{
    extern __shared__ float sm[];
    float* aS_base = sm;
    float* bS_base = sm + 2 * A_BUF;

    const int tid  = threadIdx.x;
    const int wid  = tid >> 5;
    const int lane = tid & 31;
    const int wm   = wid & 3;
    const int wn   = wid >> 2;
    const int row0 = blockIdx.x * 128;
    const int KCH  = DUAL ? 8 : 4;

    float acc[2][8][4];
#pragma unroll
    for (int mt = 0; mt < 2; mt++)
#pragma unroll
        for (int nt = 0; nt < 8; nt++)
#pragma unroll
            for (int q = 0; q < 4; q++) acc[mt][nt][q] = 0.f;

    auto prefetch = [&](int c) {
        int buf = c & 1;
        const float* Asrc = (DUAL && c >= 4) ? A1 : A0;
        int lda          = (DUAL && c >= 4) ? lda1 : lda0;
        const float* Wsrc = (DUAL && c >= 4) ? W1 : W0;
        int ko = (DUAL ? (c & 3) : c) * 32;
        float* aS = aS_base + buf * A_BUF;
        float* bS = bS_base + buf * B_BUF;
#pragma unroll
        for (int i = 0; i < 4; i++) {
            int j   = tid + i * 256;
            int r   = j >> 3;
            int kq  = j & 7;
            int grow = row0 + r;
            cp16z(aS + r * A_STRIDE + kq * 4,
                  Asrc + (size_t)grow * lda + ko + kq * 4, grow < M);
        }
#pragma unroll
        for (int i = 0; i < 4; i++) {
            int j  = tid + i * 256;
            int k  = j >> 5;
            int nq = j & 31;
            cp16(bS + k * B_STRIDE + nq * 4,
                 Wsrc + (size_t)(ko + k) * 128 + nq * 4);
        }
        CP_COMMIT();
    };

    prefetch(0);
    for (int c = 0; c < KCH; c++) {
        if (c + 1 < KCH) { prefetch(c + 1); CP_WAIT(1); }
        else             { CP_WAIT(0); }
        __syncthreads();

        const float* aS = aS_base + (c & 1) * A_BUF;
        const float* bS = bS_base + (c & 1) * B_BUF;
#pragma unroll
        for (int k16 = 0; k16 < 2; k16++) {
            const int kb = k16 * 16;
            // A fragments (m16n8k16): a0=(r,k) a1=(r+8,k) a2=(r,k+8) a3=(r+8,k+8)
            uint32_t ahi[2][4], alo[2][4];
#pragma unroll
            for (int mt = 0; mt < 2; mt++) {
                int rbase = wm * 32 + mt * 16 + (lane >> 2);
#pragma unroll
                for (int q = 0; q < 4; q++) {
                    int r  = rbase + ((q & 1) ? 8 : 0);
                    int cc = kb + (lane & 3) * 2 + ((q & 2) ? 8 : 0);
                    float2 f = *(const float2*)(aS + r * A_STRIDE + cc);
                    split_h2(f.x, f.y, ahi[mt][q], alo[mt][q]);
                }
            }
            // B fragments: b0=(k pair, n)  b1=(k pair + 8, n)
            uint32_t bhi[8][2], blo[8][2];
#pragma unroll
            for (int nt = 0; nt < 8; nt++) {
                int nn = wn * 64 + nt * 8 + (lane >> 2);
#pragma unroll
                for (int q = 0; q < 2; q++) {
                    int kk = kb + (lane & 3) * 2 + q * 8;
                    float f0 = bS[kk * B_STRIDE + nn];
                    float f1 = bS[(kk + 1) * B_STRIDE + nn];
                    split_h2(f0, f1, bhi[nt][q], blo[nt][q]);
                }
            }
#pragma unroll
            for (int mt = 0; mt < 2; mt++)
#pragma unroll
                for (int nt = 0; nt < 8; nt++) {
                    mma_f16(acc[mt][nt], ahi[mt], bhi[nt]);
                    mma_f16(acc[mt][nt], ahi[mt], blo[nt]);
                    mma_f16(acc[mt][nt], alo[mt], bhi[nt]);
                }
        }
        __syncthreads();
    }

    // ---- epilogue (accumulator layout identical to m16n8k8) ----
#pragma unroll
    for (int mt = 0; mt < 2; mt++)
#pragma unroll
        for (int half = 0; half < 2; half++) {
            int row = row0 + wm * 32 + mt * 16 + (lane >> 2) + half * 8;
            if (row >= M) continue;
            int gi = 0;
            if (GATHER) gi = gidx[row];
#pragma unroll
            for (int nt = 0; nt < 8; nt++) {
                int col = wn * 64 + nt * 8 + 2 * (lane & 3);
                float2 v = make_float2(acc[mt][nt][half * 2],
                                       acc[mt][nt][half * 2 + 1]);
                if (bias) {
                    float2 b2 = *(const float2*)(bias + col);
                    v.x += b2.x; v.y += b2.y;
                }
                if (ACCUM) {
                    float2 c2 = *(const float2*)(C + (size_t)row * 128 + col);
                    v.x += c2.x; v.y += c2.y;
                }
                if (GATHER) {
                    float2 g2 = *(const float2*)(gtab + (size_t)gi * 128 + col);
                    v.x += g2.x; v.y += g2.y;
                }
                if (RELU) { v.x = fmaxf(v.x, 0.f); v.y = fmaxf(v.y, 0.f); }
                *(float2*)(C + (size_t)row * 128 + col) = v;
            }
        }
}

// ---------------------------------------------------------------------------
// 4x fused 128x128x128 fp32 weight-product GEMM (exact; tiny)
// ---------------------------------------------------------------------------
struct WProd { const float* A[4]; const float* B[4]; float* C[4]; };

__global__ void __launch_bounds__(256) wprod_kernel(WProd wp)
{
    __shared__ float As[16][132];
    __shared__ float Wsm[16][132];
    const float* A = wp.A[blockIdx.x];
    const float* W = wp.B[blockIdx.x];
    float*       C = wp.C[blockIdx.x];

    const int tid = threadIdx.x;
    const int tx  = tid & 15;
    const int ty  = tid >> 4;
    const int ar  = tid >> 2;
    const int ac  = (tid & 3) << 2;
    const int wr  = tid >> 5;
    const int wc  = (tid & 31) << 2;

    float acc[8][8];
#pragma unroll
    for (int i = 0; i < 8; i++)
#pragma unroll
        for (int j = 0; j < 8; j++) acc[i][j] = 0.f;

    for (int k0 = 0; k0 < 128; k0 += 16) {
#pragma unroll
        for (int p = 0; p < 2; p++) {
            int r = ar + p * 64;
            float4 v = *(const float4*)(A + (size_t)r * 128 + k0 + ac);
            As[ac + 0][r] = v.x; As[ac + 1][r] = v.y;
            As[ac + 2][r] = v.z; As[ac + 3][r] = v.w;
        }
#pragma unroll
        for (int p = 0; p < 2; p++) {
            int r = wr + p * 8;
            *(float4*)&Wsm[r][wc] = *(const float4*)(W + (size_t)(k0 + r) * 128 + wc);
        }
        __syncthreads();
#pragma unroll
        for (int kk = 0; kk < 16; kk++) {
            float a[8], b[8];
            *(float4*)(a)     = *(const float4*)&As[kk][ty * 8];
            *(float4*)(a + 4) = *(const float4*)&As[kk][ty * 8 + 4];
            *(float4*)(b)     = *(const float4*)&Wsm[kk][tx * 8];
            *(float4*)(b + 4) = *(const float4*)&Wsm[kk][tx * 8 + 4];
#pragma unroll
            for (int i = 0; i < 8; i++)
#pragma unroll
                for (int j = 0; j < 8; j++)
                    acc[i][j] = fmaf(a[i], b[j], acc[i][j]);
        }
        __syncthreads();
    }
#pragma unroll
    for (int i = 0; i < 8; i++) {
        int r = ty * 8 + i;
#pragma unroll
        for (int j = 0; j < 8; j += 4)
            *(float4*)(C + (size_t)r * 128 + tx * 8 + j) =
                make_float4(acc[i][j], acc[i][j+1], acc[i][j+2], acc[i][j+3]);
    }
}

__global__ void cvec_kernel(const float* __restrict__ bc1,
                            const float* __restrict__ bl2_sp,
                            const float* __restrict__ bl2_ps,
                            const float* __restrict__ Wc1,
                            float* __restrict__ cvec)
{
    int j = threadIdx.x;
    float c = bc1[j];
    for (int k = 0; k < 128; k++) {
        c += bl2_sp[k] * Wc1[(size_t)k * 128 + j];
        c += bl2_ps[k] * Wc1[(size_t)(128 + k) * 128 + j];
    }
    cvec[j] = c;
}

// ---------------------------------------------------------------------------
// CSR build
// ---------------------------------------------------------------------------
__global__ void hist_kernel(const int* __restrict__ src, const int* __restrict__ dst,
                            int* cntP, int* cntS, int E)
{
    int i = blockIdx.x * blockDim.x + threadIdx.x;
    if (i < E) {
        atomicAdd(&cntP[src[i]], 1);
        atomicAdd(&cntS[dst[i]], 1);
    }
}

__global__ void scan1_kernel(const int* __restrict__ in, int* __restrict__ out_excl,
                             int* __restrict__ bsums, int N)
{
    __shared__ int sh[2][1024];
    int t = threadIdx.x;
    int i = blockIdx.x * 1024 + t;
    int x = (i < N) ? in[i] : 0;
    sh[0][t] = x;
    __syncthreads();
    int cur = 0;
#pragma unroll
    for (int off = 1; off < 1024; off <<= 1) {
        int v = sh[cur][t];
        if (t >= off) v += sh[cur][t - off];
        sh[cur ^ 1][t] = v;
        __syncthreads();
        cur ^= 1;
    }
    int incl = sh[cur][t];
    if (i < N) out_excl[i] = incl - x;
    if (t == 1023) bsums[blockIdx.x] = incl;
}

__global__ void scan2_kernel(int* __restrict__ b, int nb)
{
    __shared__ int sh[2][1024];
    int t = threadIdx.x;
    int x = (t < nb) ? b[t] : 0;
    sh[0][t] = x;
    __syncthreads();
    int cur = 0;
#pragma unroll
    for (int off = 1; off < 1024; off <<= 1) {
        int v = sh[cur][t];
        if (t >= off) v += sh[cur][t - off];
        sh[cur ^ 1][t] = v;
        __syncthreads();
        cur ^= 1;
    }
    if (t < nb) b[t] = sh[cur][t] - x;
}

__global__ void scan3_kernel(int* __restrict__ out, const int* __restrict__ bsums, int N)
{
    int i = blockIdx.x * blockDim.x + threadIdx.x;
    if (i < N) out[i] += bsums[i >> 10];
}

__global__ void fill_kernel(const int* __restrict__ src, const int* __restrict__ dst,
                            const int* __restrict__ offP, const int* __restrict__ offS,
                            int* curP, int* curS,
                            int* __restrict__ csrP, int* __restrict__ csrS, int E)
{
    int e = blockIdx.x * blockDim.x + threadIdx.x;
    if (e >= E) return;
    int s = src[e];
    int d = dst[e];
    int pS = offS[d] + atomicAdd(&curS[d], 1);
    csrS[pS] = s;
    int pP = offP[s] + atomicAdd(&curP[s], 1);
    csrP[pP] = d;
}

// ---------------------------------------------------------------------------
// Gather-mean aggregation (fp32 tables — R13 semantics)
// ---------------------------------------------------------------------------
__global__ void agg_kernel(const float* __restrict__ feat,
                           const int* __restrict__ off, const int* __restrict__ cnt,
                           const int* __restrict__ idx,
                           float* __restrict__ out, int M)
{
    int gtid = blockIdx.x * blockDim.x + threadIdx.x;
    int n    = gtid >> 5;
    int lane = gtid & 31;
    if (n >= M) return;
    int start = off[n];
    int deg   = cnt[n];
    float4 acc = make_float4(0.f, 0.f, 0.f, 0.f);
    int j = 0;
    for (; j + 1 < deg; j += 2) {
        int i0 = __ldg(&idx[start + j]);
        int i1 = __ldg(&idx[start + j + 1]);
        float4 v0 = *(const float4*)(feat + (size_t)i0 * 128 + lane * 4);
        float4 v1 = *(const float4*)(feat + (size_t)i1 * 128 + lane * 4);
        acc.x += v0.x + v1.x; acc.y += v0.y + v1.y;
        acc.z += v0.z + v1.z; acc.w += v0.w + v1.w;
    }
    if (j < deg) {
        int i0 = __ldg(&idx[start + j]);
        float4 v0 = *(const float4*)(feat + (size_t)i0 * 128 + lane * 4);
        acc.x += v0.x; acc.y += v0.y; acc.z += v0.z; acc.w += v0.w;
    }
    float s = 1.f / fmaxf((float)deg, 1.f);
    acc.x *= s; acc.y *= s; acc.z *= s; acc.w *= s;
    *(float4*)(out + (size_t)n * 128 + lane * 4) = acc;
}

// ---------------------------------------------------------------------------
// Edge classifier: 2 labels per warp (16 lanes each).
// ---------------------------------------------------------------------------
__global__ void classify_kernel(const float* __restrict__ up, const float* __restrict__ us,
                                const int* __restrict__ lp, const int* __restrict__ ls,
                                const float* __restrict__ cvec, const float* __restrict__ wc2,
                                const float* __restrict__ bc2,
                                float* __restrict__ out, int L)
{
    int gtid = blockIdx.x * blockDim.x + threadIdx.x;
    int l    = gtid >> 4;
    int sub  = gtid & 15;
    if (l >= L) return;
    int ip = lp[l];
    int is = ls[l];
    const float4* pa = (const float4*)(up   + (size_t)ip * 128 + sub * 8);
    const float4* pb = (const float4*)(us   + (size_t)is * 128 + sub * 8);
    const float4* pc = (const float4*)(cvec + sub * 8);
    const float4* pw = (const float4*)(wc2  + sub * 8);
    float4 a0 = pa[0], a1 = pa[1];
    float4 b0 = pb[0], b1 = pb[1];
    float4 c0 = pc[0], c1 = pc[1];
    float4 w0 = pw[0], w1 = pw[1];
    float s = fmaxf(a0.x + b0.x + c0.x, 0.f) * w0.x
            + fmaxf(a0.y + b0.y + c0.y, 0.f) * w0.y
            + fmaxf(a0.z + b0.z + c0.z, 0.f) * w0.z
            + fmaxf(a0.w + b0.w + c0.w, 0.f) * w0.w
            + fmaxf(a1.x + b1.x + c1.x, 0.f) * w1.x
            + fmaxf(a1.y + b1.y + c1.y, 0.f) * w1.y
            + fmaxf(a1.z + b1.z + c1.z, 0.f) * w1.z
            + fmaxf(a1.w + b1.w + c1.w, 0.f) * w1.w;
#pragma unroll
    for (int o = 8; o > 0; o >>= 1) s += __shfl_xor_sync(0xffffffffu, s, o);
    if (sub == 0) out[l] = s + bc2[0];
}

// ---------------------------------------------------------------------------
// Stream/event context (host-side objects only; created once)
// ---------------------------------------------------------------------------
static cudaStream_t sA, sB, sC;
static cudaEvent_t  evRoot, evHist, evScanS, evCSR, evFusS, evFusP, evW, evB,
                    evHs, evHp, evA, evC;
static int          g_streams_ok = -1;

static bool init_streams()
{
    bool ok = true;
    ok &= cudaStreamCreateWithFlags(&sA, cudaStreamNonBlocking) == cudaSuccess;
    ok &= cudaStreamCreateWithFlags(&sB, cudaStreamNonBlocking) == cudaSuccess;
    ok &= cudaStreamCreateWithFlags(&sC, cudaStreamNonBlocking) == cudaSuccess;
    cudaEvent_t* evs[12] = {&evRoot, &evHist, &evScanS, &evCSR, &evFusS, &evFusP,
                            &evW, &evB, &evHs, &evHp, &evA, &evC};
    for (int i = 0; i < 12; i++)
        ok &= cudaEventCreateWithFlags(evs[i], cudaEventDisableTiming) == cudaSuccess;
    return ok;
}

// ---------------------------------------------------------------------------
// Launch
// ---------------------------------------------------------------------------
extern "C" void kernel_launch(void* const* d_in, const int* in_sizes, int n_in,
                              void* d_out, int out_size)
{
    (void)in_sizes; (void)n_in; (void)out_size;

    const float* x_paper    = (const float*)d_in[0];
    const float* x_software = (const float*)d_in[1];
    const int*   paper_id   = (const int*)d_in[2];
    const int*   software_id= (const int*)d_in[3];
    const int*   edge_src   = (const int*)d_in[4];
    const int*   edge_dst   = (const int*)d_in[5];
    const int*   lbl_paper  = (const int*)d_in[6];
    const int*   lbl_soft   = (const int*)d_in[7];
    const float* paper_emb  = (const float*)d_in[8];
    const float* soft_emb   = (const float*)d_in[9];
    const float* Wp   = (const float*)d_in[10]; const float* bp    = (const float*)d_in[11];
    const float* Wso  = (const float*)d_in[12]; const float* bso   = (const float*)d_in[13];
    const float* Wl1_ps=(const float*)d_in[14]; const float* bl1_ps=(const float*)d_in[15];
    const float* Wr1_ps=(const float*)d_in[16];
    const float* Wl1_sp=(const float*)d_in[17]; const float* bl1_sp=(const float*)d_in[18];
    const float* Wr1_sp=(const float*)d_in[19];
    const float* Wl2_ps=(const float*)d_in[20]; const float* bl2_ps=(const float*)d_in[21];
    const float* Wr2_ps=(const float*)d_in[22];
    const float* Wl2_sp=(const float*)d_in[23]; const float* bl2_sp=(const float*)d_in[24];
    const float* Wr2_sp=(const float*)d_in[25];
    const float* Wc1  = (const float*)d_in[26]; const float* bc1   = (const float*)d_in[27];
    const float* Wc2  = (const float*)d_in[28]; const float* bc2   = (const float*)d_in[29];
    float* out = (float*)d_out;

    float *pP0, *pP1, *pP2, *pS0, *pS1, *pS2, *pS3, *pS4, *pS5, *pW4, *pCvec;
    int *pCntP, *pCntS, *pOffP, *pOffS, *pBsum, *pBsum2, *pCsrP, *pCsrS;
    cudaGetSymbolAddress((void**)&pP0, g_P0);
    cudaGetSymbolAddress((void**)&pP1, g_P1);
    cudaGetSymbolAddress((void**)&pP2, g_P2);
    cudaGetSymbolAddress((void**)&pS0, g_S0);
    cudaGetSymbolAddress((void**)&pS1, g_S1);
    cudaGetSymbolAddress((void**)&pS2, g_S2);
    cudaGetSymbolAddress((void**)&pS3, g_S3);
    cudaGetSymbolAddress((void**)&pS4, g_S4);
    cudaGetSymbolAddress((void**)&pS5, g_S5);
    cudaGetSymbolAddress((void**)&pW4, g_W4);
    cudaGetSymbolAddress((void**)&pCvec, g_cvec);
    cudaGetSymbolAddress((void**)&pCntP, g_cntP);
    cudaGetSymbolAddress((void**)&pCntS, g_cntS);
    cudaGetSymbolAddress((void**)&pOffP, g_offP);
    cudaGetSymbolAddress((void**)&pOffS, g_offS);
    cudaGetSymbolAddress((void**)&pBsum, g_bsum);
    cudaGetSymbolAddress((void**)&pBsum2, g_bsum2);
    cudaGetSymbolAddress((void**)&pCsrP, g_csrP);
    cudaGetSymbolAddress((void**)&pCsrS, g_csrS);

    cudaFuncSetAttribute(mma_gemm<true,  true,  false, false>, cudaFuncAttributeMaxDynamicSharedMemorySize, MM_SMEM);
    cudaFuncSetAttribute(mma_gemm<true,  false, false, true >, cudaFuncAttributeMaxDynamicSharedMemorySize, MM_SMEM);
    cudaFuncSetAttribute(mma_gemm<true,  false, false, false>, cudaFuncAttributeMaxDynamicSharedMemorySize, MM_SMEM);
    cudaFuncSetAttribute(mma_gemm<false, false, false, false>, cudaFuncAttributeMaxDynamicSharedMemorySize, MM_SMEM);
    cudaFuncSetAttribute(mma_gemm<false, false, true,  true >, cudaFuncAttributeMaxDynamicSharedMemorySize, MM_SMEM);
    cudaFuncSetAttribute(mma_gemm<false, false, true,  false>, cudaFuncAttributeMaxDynamicSharedMemorySize, MM_SMEM);

    if (g_streams_ok < 0) g_streams_ok = init_streams() ? 1 : 0;

    const int E = NEDGE, L = NLBL;
    const int gP = (NPAPER + 127) / 128;
    const int gS = (NSOFT  + 127) / 128;
    const int aggPBlocks = (int)(((long long)NPAPER * 32 + 255) / 256);
    const int aggSBlocks = (int)(((long long)NSOFT  * 32 + 255) / 256);
    const int nbP = (NPAPER + 1023) / 1024;
    const int nbS = (NSOFT  + 1023) / 1024;
    const int clsBlocks = (int)(((long long)L * 16 + 255) / 256);

    const float* Wc1_top = Wc1;
    const float* Wc1_bot = Wc1 + 128 * 128;
    WProd wp;
    wp.A[0] = Wl2_sp; wp.B[0] = Wc1_top; wp.C[0] = pW4 + 0 * 16384;  // WA
    wp.A[1] = Wr2_sp; wp.B[1] = Wc1_top; wp.C[1] = pW4 + 1 * 16384;  // WB
    wp.A[2] = Wl2_ps; wp.B[2] = Wc1_bot; wp.C[2] = pW4 + 2 * 16384;  // WC
    wp.A[3] = Wr2_ps; wp.B[3] = Wc1_bot; wp.C[3] = pW4 + 3 * 16384;  // WD

    if (g_streams_ok == 1) {
        // ========== forked-capture parallel schedule (R13) ==========
        cudaEventRecord(evRoot, 0);
        cudaStreamWaitEvent(sA, evRoot, 0);
        cudaStreamWaitEvent(sB, evRoot, 0);
        cudaStreamWaitEvent(sC, evRoot, 0);

        // sA: CSR build (paper scan local; software scan forked to sB)
        cudaMemsetAsync(pCntP, 0, NPAPER * sizeof(int), sA);
        cudaMemsetAsync(pCntS, 0, NSOFT  * sizeof(int), sA);
        hist_kernel<<<(E + 255) / 256, 256, 0, sA>>>(edge_src, edge_dst, pCntP, pCntS, E);
        cudaEventRecord(evHist, sA);
        scan1_kernel<<<nbP, 1024, 0, sA>>>(pCntP, pOffP, pBsum, NPAPER);
        scan2_kernel<<<1, 1024, 0, sA>>>(pBsum, nbP);
        scan3_kernel<<<(NPAPER + 255) / 256, 256, 0, sA>>>(pOffP, pBsum, NPAPER);
        cudaMemsetAsync(pCntP, 0, NPAPER * sizeof(int), sA);
        cudaStreamWaitEvent(sB, evHist, 0);
        scan1_kernel<<<nbS, 1024, 0, sB>>>(pCntS, pOffS, pBsum2, NSOFT);
        scan2_kernel<<<1, 1024, 0, sB>>>(pBsum2, nbS);
        scan3_kernel<<<(NSOFT + 255) / 256, 256, 0, sB>>>(pOffS, pBsum2, NSOFT);
        cudaMemsetAsync(pCntS, 0, NSOFT * sizeof(int), sB);
        cudaEventRecord(evScanS, sB);
        cudaStreamWaitEvent(sA, evScanS, 0);
        fill_kernel<<<(E + 255) / 256, 256, 0, sA>>>(edge_src, edge_dst, pOffP, pOffS,
                                                     pCntP, pCntS, pCsrP, pCsrS, E);
        cudaEventRecord(evCSR, sA);

        // sB: weight products + cvec
        wprod_kernel<<<4, 256, 0, sB>>>(wp);
        cudaEventRecord(evW, sB);
        cvec_kernel<<<1, 128, 0, sB>>>(bc1, bl2_sp, bl2_ps, Wc1, pCvec);
        cudaEventRecord(evB, sB);

        // s0: paper input fusion (largest GEMM)
        mma_gemm<true, true, false, false><<<gP, 256, MM_SMEM>>>(
            x_paper, 256, x_paper + 128, 256, Wp, Wp + 128 * 128,
            bp, paper_emb, paper_id, pP0, NPAPER);
        cudaEventRecord(evFusP, 0);

        // sC: software fusion -> sp-direction chain -> h_p
        mma_gemm<true, true, false, false><<<gS, 256, MM_SMEM, sC>>>(
            x_software, 256, x_software + 128, 256, Wso, Wso + 128 * 128,
            bso, soft_emb, software_id, pS0, NSOFT);
        cudaEventRecord(evFusS, sC);
        mma_gemm<false, false, false, false><<<gS, 256, MM_SMEM, sC>>>(
            pS0, 128, nullptr, 0, Wl1_sp, nullptr,
            nullptr, nullptr, nullptr, pS4, NSOFT);
        cudaStreamWaitEvent(sC, evCSR, 0);
        agg_kernel<<<aggPBlocks, 256, 0, sC>>>(pS4, pOffP, pCntP, pCsrP, pP1, NPAPER);
        cudaStreamWaitEvent(sC, evFusP, 0);
        mma_gemm<false, false, true, true><<<gP, 256, MM_SMEM, sC>>>(
            pP0, 128, nullptr, 0, Wr1_sp, nullptr,
            bl1_sp, nullptr, nullptr, pP1, NPAPER);                  // h_p
        cudaEventRecord(evHp, sC);

        // sA: ps-direction chain + u_p chain
        cudaStreamWaitEvent(sA, evFusP, 0);
        agg_kernel<<<aggSBlocks, 256, 0, sA>>>(pP0, pOffS, pCntS, pCsrS, pS3, NSOFT);
        cudaStreamWaitEvent(sA, evFusS, 0);
        mma_gemm<true, false, false, true><<<gS, 256, MM_SMEM, sA>>>(
            pS3, 128, pS0, 128, Wl1_ps, Wr1_ps,
            bl1_ps, nullptr, nullptr, pS1, NSOFT);                   // h_s
        cudaEventRecord(evHs, sA);
        cudaStreamWaitEvent(sA, evW, 0);
        mma_gemm<false, false, false, false><<<gS, 256, MM_SMEM, sA>>>(
            pS1, 128, nullptr, 0, pW4 + 0 * 16384, nullptr,
            nullptr, nullptr, nullptr, pS5, NSOFT);                  // h_s @ WA
        agg_kernel<<<aggPBlocks, 256, 0, sA>>>(pS5, pOffP, pCntP, pCsrP, pP2, NPAPER);
        cudaStreamWaitEvent(sA, evHp, 0);
        mma_gemm<false, false, true, false><<<gP, 256, MM_SMEM, sA>>>(
            pP1, 128, nullptr, 0, pW4 + 1 * 16384, nullptr,
            nullptr, nullptr, nullptr, pP2, NPAPER);                 // u_p (accum P2)
        cudaEventRecord(evA, sA);

        // sC: u_s chain (after h_p on same stream)
        agg_kernel<<<aggSBlocks, 256, 0, sC>>>(pP1, pOffS, pCntS, pCsrS, pS4, NSOFT);
        cudaStreamWaitEvent(sC, evHs, 0);
        cudaStreamWaitEvent(sC, evW, 0);
        mma_gemm<true, false, false, false><<<gS, 256, MM_SMEM, sC>>>(
            pS4, 128, pS1, 128, pW4 + 2 * 16384, pW4 + 3 * 16384,
            nullptr, nullptr, nullptr, pS2, NSOFT);                  // u_s
        cudaEventRecord(evC, sC);

        // s0: join + classify
        cudaStreamWaitEvent(0, evA, 0);
        cudaStreamWaitEvent(0, evC, 0);
        cudaStreamWaitEvent(0, evB, 0);
        classify_kernel<<<clsBlocks, 256>>>(
            pP2, pS2, lbl_paper, lbl_soft, pCvec, Wc2, bc2, out, L);
    } else {
        // ================= serial fallback =================
        cudaMemsetAsync(pCntP, 0, NPAPER * sizeof(int));
        cudaMemsetAsync(pCntS, 0, NSOFT  * sizeof(int));
        hist_kernel<<<(E + 255) / 256, 256>>>(edge_src, edge_dst, pCntP, pCntS, E);
        scan1_kernel<<<nbS, 1024>>>(pCntS, pOffS, pBsum2, NSOFT);
        scan2_kernel<<<1, 1024>>>(pBsum2, nbS);
        scan3_kernel<<<(NSOFT + 255) / 256, 256>>>(pOffS, pBsum2, NSOFT);
        scan1_kernel<<<nbP, 1024>>>(pCntP, pOffP, pBsum, NPAPER);
        scan2_kernel<<<1, 1024>>>(pBsum, nbP);
        scan3_kernel<<<(NPAPER + 255) / 256, 256>>>(pOffP, pBsum, NPAPER);
        cudaMemsetAsync(pCntP, 0, NPAPER * sizeof(int));
        cudaMemsetAsync(pCntS, 0, NSOFT  * sizeof(int));
        fill_kernel<<<(E + 255) / 256, 256>>>(edge_src, edge_dst, pOffP, pOffS,
                                              pCntP, pCntS, pCsrP, pCsrS, E);
        wprod_kernel<<<4, 256>>>(wp);
        cvec_kernel<<<1, 128>>>(bc1, bl2_sp, bl2_ps, Wc1, pCvec);
        mma_gemm<true, true, false, false><<<gP, 256, MM_SMEM>>>(
            x_paper, 256, x_paper + 128, 256, Wp, Wp + 128 * 128,
            bp, paper_emb, paper_id, pP0, NPAPER);
        mma_gemm<true, true, false, false><<<gS, 256, MM_SMEM>>>(
            x_software, 256, x_software + 128, 256, Wso, Wso + 128 * 128,
            bso, soft_emb, software_id, pS0, NSOFT);
        agg_kernel<<<aggSBlocks, 256>>>(pP0, pOffS, pCntS, pCsrS, pS3, NSOFT);
        mma_gemm<true, false, false, true><<<gS, 256, MM_SMEM>>>(
            pS3, 128, pS0, 128, Wl1_ps, Wr1_ps,
            bl1_ps, nullptr, nullptr, pS1, NSOFT);
        mma_gemm<false, false, false, false><<<gS, 256, MM_SMEM>>>(
            pS0, 128, nullptr, 0, Wl1_sp, nullptr,
            nullptr, nullptr, nullptr, pS4, NSOFT);
        agg_kernel<<<aggPBlocks, 256>>>(pS4, pOffP, pCntP, pCsrP, pP1, NPAPER);
        mma_gemm<false, false, true, true><<<gP, 256, MM_SMEM>>>(
            pP0, 128, nullptr, 0, Wr1_sp, nullptr,
            bl1_sp, nullptr, nullptr, pP1, NPAPER);
        mma_gemm<false, false, false, false><<<gS, 256, MM_SMEM>>>(
            pS1, 128, nullptr, 0, pW4 + 0 * 16384, nullptr,
            nullptr, nullptr, nullptr, pS5, NSOFT);
        agg_kernel<<<aggPBlocks, 256>>>(pS5, pOffP, pCntP, pCsrP, pP2, NPAPER);
        mma_gemm<false, false, true, false><<<gP, 256, MM_SMEM>>>(
            pP1, 128, nullptr, 0, pW4 + 1 * 16384, nullptr,
            nullptr, nullptr, nullptr, pP2, NPAPER);
        agg_kernel<<<aggSBlocks, 256>>>(pP1, pOffS, pCntS, pCsrS, pS4, NSOFT);
        mma_gemm<true, false, false, false><<<gS, 256, MM_SMEM>>>(
            pS4, 128, pS1, 128, pW4 + 2 * 16384, pW4 + 3 * 16384,
            nullptr, nullptr, nullptr, pS2, NSOFT);
        classify_kernel<<<clsBlocks, 256>>>(
            pP2, pS2, lbl_paper, lbl_soft, pCvec, Wc2, bc2, out, L);
    }
}